// round 15
// baseline (speedup 1.0000x reference)
#include <cuda_runtime.h>
#include <cuda_bf16.h>
#include <math.h>
#include <stdint.h>

#define NMAX 50000
#define NPAD 50176
#define EMAX 600000
#define GMAX 128
#define SCAN_BLK 4096

// ---------------- scratch ----------------
__device__ __align__(16) float g_xn[NPAD * 128];
__device__ __align__(16) float g_mean[NPAD * 128];
__device__ __align__(16) float g_t[NPAD * 128];
__device__ __align__(16) float g_h1[NPAD * 128];
__device__ __align__(16) float g_h[NPAD * 128];
__device__ __align__(16) int g_rowptr[NMAX + 8];
__device__ __align__(16) int g_fill[NMAX + 8];
__device__ int g_col[EMAX];
__device__ int g_src[EMAX];
__device__ int g_dst[EMAX];
__device__ int g_batch[NMAX + 8];
__device__ int g_blksum[64];
__device__ int g_is64;

// ---------------- tf32 helpers ----------------
__device__ __forceinline__ uint32_t f2tf32(float f) {
    uint32_t r;
    asm("cvt.rna.tf32.f32 %0, %1;" : "=r"(r) : "f"(f));
    return r;
}
__device__ __forceinline__ void mma_tf32_16n8k8(float* d, const uint32_t* a, const uint32_t* b) {
    asm volatile(
        "mma.sync.aligned.m16n8k8.row.col.f32.tf32.tf32.f32 "
        "{%0,%1,%2,%3}, {%4,%5,%6,%7}, {%8,%9}, {%0,%1,%2,%3};"
        : "+f"(d[0]), "+f"(d[1]), "+f"(d[2]), "+f"(d[3])
        : "r"(a[0]), "r"(a[1]), "r"(a[2]), "r"(a[3]), "r"(b[0]), "r"(b[1]));
}
__device__ __forceinline__ int swz(int g) { return g ^ (g >> 3); }

// ---------------- init: block 0 probes dtype, rest zero degree array --------
__global__ void k_init(const void* raw, int count, int nlimit, int* flag,
                       int* __restrict__ fill, int n) {
    if (blockIdx.x == 0) {
        __shared__ int ok;
        if (threadIdx.x == 0) ok = 1;
        __syncthreads();
        int m = count / 2 < 1024 ? count / 2 : 1024;
        const long long* p = (const long long*)raw;
        for (int i = threadIdx.x; i < m; i += blockDim.x) {
            long long v = p[i];
            if (v < 0 || v >= (long long)nlimit) ok = 0;
        }
        __syncthreads();
        if (threadIdx.x == 0) *flag = ok;
    } else {
        int i = (blockIdx.x - 1) * blockDim.x + threadIdx.x;
        if (i < n) fill[i] = 0;
    }
}

// ---------------- phase 2: edge convert+count | batch convert | preprocess --
__global__ void k_phase2(const void* eraw, int E, const int* flag,
                         int* __restrict__ src, int* __restrict__ dst,
                         int* __restrict__ deg,
                         const void* braw, int n, int* __restrict__ batch,
                         const float* __restrict__ x, float* __restrict__ xn,
                         int PB, int BB) {
    int b = blockIdx.x;
    if (b < PB) {
        int e0 = (b * blockDim.x + threadIdx.x) * 2;
        if (e0 >= E) return;
        int s0, d0, s1, d1;
        bool two = (e0 + 1 < E);
        if (*flag) {
            const long long* p = (const long long*)eraw;
            longlong2 sv = *(const longlong2*)(p + e0);
            longlong2 dv = *(const longlong2*)(p + E + e0);
            s0 = (int)sv.x; s1 = (int)sv.y;
            d0 = (int)dv.x; d1 = (int)dv.y;
        } else {
            const int* p = (const int*)eraw;
            s0 = p[e0]; d0 = p[E + e0];
            s1 = two ? p[e0 + 1] : 0;
            d1 = two ? p[E + e0 + 1] : 0;
        }
        src[e0] = s0; dst[e0] = d0;
        atomicAdd(&deg[d0], 1);
        if (two) {
            src[e0 + 1] = s1; dst[e0 + 1] = d1;
            atomicAdd(&deg[d1], 1);
        }
    } else if (b < PB + BB) {
        int i0 = ((b - PB) * blockDim.x + threadIdx.x) * 4;
        if (i0 >= n) return;
        if (*flag) {
            const long long* p = (const long long*)braw;
#pragma unroll
            for (int q = 0; q < 4; ++q)
                if (i0 + q < n) batch[i0 + q] = (int)p[i0 + q];
        } else {
            const int* p = (const int*)braw;
#pragma unroll
            for (int q = 0; q < 4; ++q)
                if (i0 + q < n) batch[i0 + q] = p[i0 + q];
        }
    } else {
        int w = (((b - PB - BB) * blockDim.x) + threadIdx.x) >> 5;
        if (w >= n) return;
        int lane = threadIdx.x & 31;
        float4 v = *(const float4*)(x + (size_t)w * 128 + lane * 4);
        float s = v.x + v.y + v.z + v.w;
#pragma unroll
        for (int o = 16; o > 0; o >>= 1) s += __shfl_xor_sync(0xffffffffu, s, o);
        float rinv = (s != 0.f) ? (1.f / s) : 0.f;
        *(float4*)(xn + (size_t)w * 128 + lane * 4) =
            make_float4(v.x * rinv, v.y * rinv, v.z * rinv, v.w * rinv);
    }
}

// ---------------- 2-phase scan ----------------
__global__ void k_scan_p1(const int* __restrict__ deg, int* __restrict__ rowptr,
                          int* __restrict__ fill, int* __restrict__ blksum, int n) {
    __shared__ int wsum[32];
    int t = threadIdx.x, lane = t & 31, wid = t >> 5;
    int i0 = blockIdx.x * SCAN_BLK + t * 4;
    int v[4];
    if (i0 + 3 < n) {
        int4 d = *(const int4*)(deg + i0);
        v[0] = d.x; v[1] = d.y; v[2] = d.z; v[3] = d.w;
    } else {
#pragma unroll
        for (int q = 0; q < 4; ++q) v[q] = (i0 + q < n) ? deg[i0 + q] : 0;
    }
    int s = v[0] + v[1] + v[2] + v[3];
    int xv = s;
#pragma unroll
    for (int o = 1; o < 32; o <<= 1) {
        int y = __shfl_up_sync(0xffffffffu, xv, o);
        if (lane >= o) xv += y;
    }
    if (lane == 31) wsum[wid] = xv;
    __syncthreads();
    if (wid == 0) {
        int wv = wsum[lane];
#pragma unroll
        for (int o = 1; o < 32; o <<= 1) {
            int y = __shfl_up_sync(0xffffffffu, wv, o);
            if (lane >= o) wv += y;
        }
        wsum[lane] = wv;
        if (lane == 31) blksum[blockIdx.x] = wv;
    }
    __syncthreads();
    int run = (xv - s) + (wid > 0 ? wsum[wid - 1] : 0);
    if (i0 + 3 < n) {
        int4 rp = make_int4(run, run + v[0], run + v[0] + v[1], run + v[0] + v[1] + v[2]);
        *(int4*)(rowptr + i0) = rp;
        *(int4*)(fill + i0) = rp;
    } else {
#pragma unroll
        for (int q = 0; q < 4; ++q)
            if (i0 + q < n) { rowptr[i0 + q] = run; fill[i0 + q] = run; run += v[q]; }
    }
}

__global__ void k_scan_p3(int* __restrict__ rowptr, int* __restrict__ fill,
                          const int* __restrict__ blksum, int n, int nb) {
    __shared__ int s_off, s_tot;
    if (threadIdx.x < 32) {
        int v = (threadIdx.x < nb) ? blksum[threadIdx.x] : 0;
        int xv = v;
#pragma unroll
        for (int o = 1; o < 32; o <<= 1) {
            int y = __shfl_up_sync(0xffffffffu, xv, o);
            if ((threadIdx.x & 31) >= o) xv += y;
        }
        if (threadIdx.x == 31) s_tot = xv;
        if (threadIdx.x == blockIdx.x) s_off = xv - v;
    }
    __syncthreads();
    int off = s_off;
    int i0 = blockIdx.x * SCAN_BLK + threadIdx.x * 4;
    if (blockIdx.x == 0) {
        if (threadIdx.x == 0) rowptr[n] = s_tot;
        return;
    }
    if (i0 + 3 < n) {
        int4 r = *(const int4*)(rowptr + i0);
        r.x += off; r.y += off; r.z += off; r.w += off;
        *(int4*)(rowptr + i0) = r;
        *(int4*)(fill + i0) = r;
    } else {
#pragma unroll
        for (int q = 0; q < 4; ++q)
            if (i0 + q < n) { int r = rowptr[i0 + q] + off; rowptr[i0 + q] = r; fill[i0 + q] = r; }
    }
}

__global__ void k_fill_edges(const int* __restrict__ src, const int* __restrict__ dst,
                             int* __restrict__ fillc, int* __restrict__ col, int E) {
    int e = blockIdx.x * blockDim.x + threadIdx.x;
    if (e < E) {
        int p = atomicAdd(&fillc[dst[e]], 1);
        col[p] = src[e];
    }
}

// ---------------- mean aggregation (PDL: trigger + gridsync at entry) -------
__global__ void k_aggregate(const float* __restrict__ xin, const int* __restrict__ rowptr,
                            const int* __restrict__ col, float* __restrict__ outm, int n) {
#if __CUDA_ARCH__ >= 900
    cudaTriggerProgrammaticLaunchCompletion();
    cudaGridDependencySynchronize();
#endif
    int w = (blockIdx.x * blockDim.x + threadIdx.x) >> 5;
    if (w >= n) return;
    int lane = threadIdx.x & 31;
    int s0 = rowptr[w], s1 = rowptr[w + 1];
    float ax = 0.f, ay = 0.f, az = 0.f, aw = 0.f;
    int j = s0;
    for (; j + 3 < s1; j += 4) {
        int i0 = __ldg(&col[j]);
        int i1 = __ldg(&col[j + 1]);
        int i2 = __ldg(&col[j + 2]);
        int i3 = __ldg(&col[j + 3]);
        float4 v0 = *(const float4*)(xin + (size_t)i0 * 128 + lane * 4);
        float4 v1 = *(const float4*)(xin + (size_t)i1 * 128 + lane * 4);
        float4 v2 = *(const float4*)(xin + (size_t)i2 * 128 + lane * 4);
        float4 v3 = *(const float4*)(xin + (size_t)i3 * 128 + lane * 4);
        ax += v0.x + v1.x + v2.x + v3.x;
        ay += v0.y + v1.y + v2.y + v3.y;
        az += v0.z + v1.z + v2.z + v3.z;
        aw += v0.w + v1.w + v2.w + v3.w;
    }
    for (; j < s1; ++j) {
        int s = __ldg(&col[j]);
        float4 v = *(const float4*)(xin + (size_t)s * 128 + lane * 4);
        ax += v.x; ay += v.y; az += v.z; aw += v.w;
    }
    float inv = 1.f / fmaxf((float)(s1 - s0), 1.f);
    *(float4*)(outm + (size_t)w * 128 + lane * 4) = make_float4(ax * inv, ay * inv, az * inv, aw * inv);
}

// ======= R11 GEMM (frozen) + PDL: stage weights pre-sync, then gridsync ======
#define SM_WF     0
#define SM_AF0    32768
#define SM_AF1    (SM_AF0 + 4096)
#define SM_BS     (SM_AF1 + 4096)
#define SM_RSS    (SM_BS + 128)
#define SM_FLOATS (SM_RSS + 128)
#define FLAG_LEAKY 1
#define FLAG_NORM  2

__global__ void __launch_bounds__(256, 1)
k_gemm_mma(const float* __restrict__ A0, const float* __restrict__ A1,
           const float* __restrict__ Wa, const float* __restrict__ Wb, int ldw,
           const float* __restrict__ bias, float* __restrict__ out, int n, int flags) {
    extern __shared__ float sm[];
    float* Wf    = sm + SM_WF;
    float* bs    = sm + SM_BS;
    float* rowss = sm + SM_RSS;

    int tid = threadIdx.x, lane = tid & 31, wid = tid >> 5;
    int wm = wid >> 2, wn = wid & 3;

#if __CUDA_ARCH__ >= 900
    cudaTriggerProgrammaticLaunchCompletion();
#endif

    if (tid < 128) bs[tid] = bias ? bias[tid] : 0.f;

    // stage weights into fragment order (inputs only -> safe before gridsync)
    for (int it = 0; it < 32; ++it) {
        int idx4 = it * 256 + tid;
        int nn = idx4 >> 6;
        int k4 = (idx4 & 63) * 4;
        float4 v = (k4 < 128) ? *(const float4*)(Wa + (size_t)nn * ldw + k4)
                              : *(const float4*)(Wb + (size_t)nn * ldw + (k4 - 128));
        float vv[4] = {v.x, v.y, v.z, v.w};
#pragma unroll
        for (int q = 0; q < 4; ++q) {
            int k = k4 + q;
            int kb = k >> 3, kc = k & 7, nt = nn >> 3, nl = nn & 7;
            Wf[(kb * 16 + nt) * 64 + (nl * 4 + (kc & 3)) * 2 + (kc >> 2)] = __uint_as_float(f2tf32(vv[q]));
        }
    }
    __syncthreads();
#if __CUDA_ARCH__ >= 900
    cudaGridDependencySynchronize();
#endif

    int numTiles = (n + 127) >> 7;
    int r = tid >> 1, ch = tid & 1;
    int mt_s = r >> 4, lrr = r & 7, rh = (r >> 3) & 1;

    for (int tile = blockIdx.x; tile < numTiles; tile += gridDim.x) {
        int row0 = tile << 7;
        float acc[4][4][4];
#pragma unroll
        for (int i = 0; i < 4; ++i)
#pragma unroll
            for (int j = 0; j < 4; ++j)
#pragma unroll
                for (int q = 0; q < 4; ++q) acc[i][j][q] = 0.f;

        {
            const float* rowp = A0 + (size_t)(row0 + r) * 128 + ch * 16;
            float* buf = sm + SM_AF0;
#pragma unroll
            for (int q = 0; q < 4; ++q) {
                float4 v = *(const float4*)(rowp + q * 4);
                float vv[4] = {v.x, v.y, v.z, v.w};
                int blk = (ch * 2 + (q >> 1)) * 8 + mt_s;
                int hh = q & 1;
#pragma unroll
                for (int j = 0; j < 4; ++j)
                    buf[blk * 128 + swz(lrr * 4 + j) * 4 + rh + 2 * hh] = __uint_as_float(f2tf32(vv[j]));
            }
        }
        __syncthreads();

        for (int c = 0; c < 8; ++c) {
            float pv[16];
            if (c < 7) {
                int cn = c + 1;
                const float* srcp = (cn < 4) ? A0 : A1;
                const float* rowp = srcp + (size_t)(row0 + r) * 128 + (cn & 3) * 32 + ch * 16;
#pragma unroll
                for (int q = 0; q < 4; ++q) {
                    float4 v = *(const float4*)(rowp + q * 4);
                    pv[q * 4 + 0] = v.x; pv[q * 4 + 1] = v.y; pv[q * 4 + 2] = v.z; pv[q * 4 + 3] = v.w;
                }
            }
            const float* Ab = sm + ((c & 1) ? SM_AF1 : SM_AF0);
#pragma unroll
            for (int h = 0; h < 4; ++h) {
                int kb = c * 4 + h;
                uint32_t a[4][4], b[4][2];
#pragma unroll
                for (int i = 0; i < 4; ++i) {
                    float4 af = *(const float4*)(Ab + (h * 8 + wm * 4 + i) * 128 + swz(lane) * 4);
                    a[i][0] = __float_as_uint(af.x);
                    a[i][1] = __float_as_uint(af.y);
                    a[i][2] = __float_as_uint(af.z);
                    a[i][3] = __float_as_uint(af.w);
                }
#pragma unroll
                for (int j = 0; j < 4; ++j) {
                    float2 bf = *(const float2*)(Wf + (kb * 16 + wn * 4 + j) * 64 + lane * 2);
                    b[j][0] = __float_as_uint(bf.x);
                    b[j][1] = __float_as_uint(bf.y);
                }
#pragma unroll
                for (int i = 0; i < 4; ++i)
#pragma unroll
                    for (int j = 0; j < 4; ++j)
                        mma_tf32_16n8k8(acc[i][j], a[i], b[j]);
            }
            if (c < 7) {
                float* buf = sm + (((c + 1) & 1) ? SM_AF1 : SM_AF0);
#pragma unroll
                for (int q = 0; q < 4; ++q) {
                    int blk = (ch * 2 + (q >> 1)) * 8 + mt_s;
                    int hh = q & 1;
#pragma unroll
                    for (int j = 0; j < 4; ++j)
                        buf[blk * 128 + swz(lrr * 4 + j) * 4 + rh + 2 * hh] = __uint_as_float(f2tf32(pv[q * 4 + j]));
                }
            }
            __syncthreads();
        }

        // ---------------- epilogue (R11 atomic version) ----------------
        int lr = lane >> 2, lc = lane & 3;
        bool donorm = (flags & FLAG_NORM) != 0;
        if (donorm) {
            if (tid < 128) rowss[tid] = 0.f;
            __syncthreads();
#pragma unroll
            for (int i = 0; i < 4; ++i) {
#pragma unroll
                for (int rh2 = 0; rh2 < 2; ++rh2) {
                    float ss = 0.f;
#pragma unroll
                    for (int j = 0; j < 4; ++j) {
                        float d0 = acc[i][j][rh2 * 2], d1 = acc[i][j][rh2 * 2 + 1];
                        ss += d0 * d0 + d1 * d1;
                    }
                    ss += __shfl_xor_sync(0xffffffffu, ss, 1);
                    ss += __shfl_xor_sync(0xffffffffu, ss, 2);
                    if (lc == 0) atomicAdd(&rowss[wm * 64 + i * 16 + lr + rh2 * 8], ss);
                }
            }
            __syncthreads();
        }
#pragma unroll
        for (int i = 0; i < 4; ++i) {
#pragma unroll
            for (int rh2 = 0; rh2 < 2; ++rh2) {
                int rl = wm * 64 + i * 16 + lr + rh2 * 8;
                int row = row0 + rl;
                if (row >= n) continue;
                float inv = 1.f;
                if (donorm) inv = 1.f / fmaxf(sqrtf(rowss[rl]), 1e-12f);
#pragma unroll
                for (int j = 0; j < 4; ++j) {
                    int colp = wn * 32 + j * 8 + 2 * lc;
                    float v0 = acc[i][j][rh2 * 2] * inv + bs[colp];
                    float v1 = acc[i][j][rh2 * 2 + 1] * inv + bs[colp + 1];
                    v0 = (v0 >= 0.f) ? v0 : 0.01f * v0;
                    v1 = (v1 >= 0.f) ? v1 : 0.01f * v1;
                    *(float2*)(out + (size_t)row * 128 + colp) = make_float2(v0, v1);
                }
            }
        }
        __syncthreads();
    }
}

// ---------------- fused pool + final (PDL gridsync at entry) ----------------
__global__ void k_poolfinal(const float* __restrict__ hin, const int* __restrict__ batch,
                            const float* __restrict__ W, const float* __restrict__ b,
                            float* __restrict__ outp, int n) {
#if __CUDA_ARCH__ >= 900
    cudaGridDependencySynchronize();
#endif
    __shared__ float pr2[256];
    __shared__ float pr[128];
    __shared__ float red[128];
    int g = blockIdx.x, tid = threadIdx.x;
    int f = tid & 127, half = tid >> 7;

    int lo = 0, hi = n;
    while (lo < hi) { int m = (lo + hi) >> 1; if (batch[m] < g) lo = m + 1; else hi = m; }
    int start = lo;
    hi = n;
    while (lo < hi) { int m = (lo + hi) >> 1; if (batch[m] < g + 1) lo = m + 1; else hi = m; }
    int end = lo;

    float acc = 0.f;
    for (int i = start + half; i < end; i += 2) acc += hin[(size_t)i * 128 + f];
    pr2[tid] = acc;
    __syncthreads();
    if (tid < 128) pr[tid] = pr2[tid] + pr2[tid + 128];
    __syncthreads();

    float a2 = 0.f;
    if (tid < 128) {
        a2 = b[tid];
#pragma unroll 8
        for (int k = 0; k < 128; ++k) a2 += pr[k] * __ldg(&W[tid * 128 + k]);
        a2 = (a2 >= 0.f) ? a2 : 0.01f * a2;
        red[tid] = a2 * a2;
    }
    __syncthreads();
    for (int s = 64; s > 0; s >>= 1) {
        if (tid < s) red[tid] += red[tid + s];
        __syncthreads();
    }
    if (tid < 128) {
        float inv = 1.f / fmaxf(sqrtf(red[0]), 1e-12f);
        outp[g * 128 + tid] = a2 * inv;
    }
}

// ---------------- launcher ----------------
static void launch_pdl_gemm(dim3 grid, dim3 block, int smem,
                            const float* A0, const float* A1,
                            const float* Wa, const float* Wb, int ldw,
                            const float* bias, float* out, int n, int flags) {
    cudaLaunchConfig_t cfg = {};
    cfg.gridDim = grid; cfg.blockDim = block;
    cfg.dynamicSmemBytes = (size_t)smem;
    cfg.stream = 0;
    cudaLaunchAttribute at[1];
    at[0].id = cudaLaunchAttributeProgrammaticStreamSerialization;
    at[0].val.programmaticStreamSerializationAllowed = 1;
    cfg.attrs = at; cfg.numAttrs = 1;
    cudaLaunchKernelEx(&cfg, k_gemm_mma, A0, A1, Wa, Wb, ldw, bias, out, n, flags);
}

static void launch_pdl_agg(dim3 grid, dim3 block,
                           const float* xin, const int* rowptr, const int* col,
                           float* outm, int n) {
    cudaLaunchConfig_t cfg = {};
    cfg.gridDim = grid; cfg.blockDim = block;
    cfg.stream = 0;
    cudaLaunchAttribute at[1];
    at[0].id = cudaLaunchAttributeProgrammaticStreamSerialization;
    at[0].val.programmaticStreamSerializationAllowed = 1;
    cfg.attrs = at; cfg.numAttrs = 1;
    cudaLaunchKernelEx(&cfg, k_aggregate, xin, rowptr, col, outm, n);
}

extern "C" void kernel_launch(void* const* d_in, const int* in_sizes, int n_in,
                              void* d_out, int out_size) {
    const float* x         = (const float*)d_in[0];
    const void*  eidx_raw  = d_in[1];
    const void*  batch_raw = d_in[2];
    const float* W1l  = (const float*)d_in[3];
    const float* W1r  = (const float*)d_in[4];
    const float* W2l  = (const float*)d_in[5];
    const float* W2r  = (const float*)d_in[6];
    const float* fc1W = (const float*)d_in[7];
    const float* fc1b = (const float*)d_in[8];
    const float* fc2W = (const float*)d_in[9];
    const float* fc2b = (const float*)d_in[10];
    const float* fc3W = (const float*)d_in[11];
    const float* fc3b = (const float*)d_in[12];
    float* out = (float*)d_out;

    int n = in_sizes[0] / 128;
    int E = in_sizes[1] / 2;

    float *xn, *tb, *h1, *h, *mean;
    int *rowptr, *fill, *col, *srcA, *dstA, *batch32, *is64, *blksum;
    cudaGetSymbolAddress((void**)&xn,      g_xn);
    cudaGetSymbolAddress((void**)&tb,      g_t);
    cudaGetSymbolAddress((void**)&h1,      g_h1);
    cudaGetSymbolAddress((void**)&h,       g_h);
    cudaGetSymbolAddress((void**)&rowptr,  g_rowptr);
    cudaGetSymbolAddress((void**)&fill,    g_fill);
    cudaGetSymbolAddress((void**)&col,     g_col);
    cudaGetSymbolAddress((void**)&srcA,    g_src);
    cudaGetSymbolAddress((void**)&dstA,    g_dst);
    cudaGetSymbolAddress((void**)&batch32, g_batch);
    cudaGetSymbolAddress((void**)&is64,    g_is64);
    cudaGetSymbolAddress((void**)&blksum,  g_blksum);
    cudaGetSymbolAddress((void**)&mean,    g_mean);

    int smemFull = SM_FLOATS * (int)sizeof(float);
    cudaFuncSetAttribute(k_gemm_mma, cudaFuncAttributeMaxDynamicSharedMemorySize, smemFull);

    int warpBlocks = (n * 32 + 255) / 256;
    int intBlocks  = (n + 255) / 256;
    int edgeBlocks = (E + 255) / 256;
    int pairBlocks = (E / 2 + 255) / 256;
    int b4Blocks   = (n / 4 + 255) / 256 + 1;
    int scanBlocks = (n + SCAN_BLK - 1) / SCAN_BLK;

    k_init<<<intBlocks + 1, 256>>>(eidx_raw, 2 * E, n, is64, fill, n);
    k_phase2<<<pairBlocks + b4Blocks + warpBlocks, 256>>>(
        eidx_raw, E, is64, srcA, dstA, fill,
        batch_raw, n, batch32, x, xn, pairBlocks, b4Blocks);

    k_scan_p1<<<scanBlocks, 1024>>>(fill, rowptr, fill, blksum, n);
    k_scan_p3<<<scanBlocks, 1024>>>(rowptr, fill, blksum, n, scanBlocks);
    k_fill_edges<<<edgeBlocks, 256>>>(srcA, dstA, fill, col, E);

    // conv1
    launch_pdl_agg(dim3(warpBlocks), dim3(256), xn, rowptr, col, mean, n);
    launch_pdl_gemm(dim3(148), dim3(256), smemFull, mean, xn, W1l, W1r, 128,
                    (const float*)nullptr, h1, n, FLAG_LEAKY | FLAG_NORM);

    // fc1
    launch_pdl_gemm(dim3(148), dim3(256), smemFull, h1, xn, fc1W, fc1W + 128, 256,
                    fc1b, h, n, FLAG_LEAKY);

    // conv2
    launch_pdl_agg(dim3(warpBlocks), dim3(256), h, rowptr, col, mean, n);
    launch_pdl_gemm(dim3(148), dim3(256), smemFull, mean, h, W2l, W2r, 128,
                    (const float*)nullptr, h1, n, FLAG_LEAKY | FLAG_NORM);

    // fc2
    launch_pdl_gemm(dim3(148), dim3(256), smemFull, h1, h, fc2W, fc2W + 128, 256,
                    fc2b, tb, n, FLAG_LEAKY);

    // fused pool + final (PDL)
    {
        cudaLaunchConfig_t cfg = {};
        cfg.gridDim = dim3(GMAX); cfg.blockDim = dim3(256);
        cfg.stream = 0;
        cudaLaunchAttribute at[1];
        at[0].id = cudaLaunchAttributeProgrammaticStreamSerialization;
        at[0].val.programmaticStreamSerializationAllowed = 1;
        cfg.attrs = at; cfg.numAttrs = 1;
        cudaLaunchKernelEx(&cfg, k_poolfinal, (const float*)tb, (const int*)batch32,
                           fc3W, fc3b, out, n);
    }
}

// round 16
// speedup vs baseline: 1.1779x; 1.1779x over previous
#include <cuda_runtime.h>
#include <cuda_bf16.h>
#include <math.h>
#include <stdint.h>

#define NMAX 50000
#define NPAD 50176
#define EMAX 600000
#define GMAX 128
#define SCAN_BLK 4096

// ---------------- scratch ----------------
__device__ __align__(16) float g_xn[NPAD * 128];
__device__ __align__(16) float g_mean[NPAD * 128];
__device__ __align__(16) float g_t[NPAD * 128];
__device__ __align__(16) float g_h1[NPAD * 128];
__device__ __align__(16) float g_h[NPAD * 128];
__device__ __align__(16) int g_rowptr[NMAX + 8];
__device__ __align__(16) int g_fill[NMAX + 8];
__device__ int g_col[EMAX];
__device__ int g_src[EMAX];
__device__ int g_dst[EMAX];
__device__ int g_batch[NMAX + 8];
__device__ int g_blksum[64];
__device__ int g_is64;

// ---------------- tf32 helpers ----------------
__device__ __forceinline__ uint32_t f2tf32(float f) {
    uint32_t r;
    asm("cvt.rna.tf32.f32 %0, %1;" : "=r"(r) : "f"(f));
    return r;
}
__device__ __forceinline__ void mma_tf32_16n8k8(float* d, const uint32_t* a, const uint32_t* b) {
    asm volatile(
        "mma.sync.aligned.m16n8k8.row.col.f32.tf32.tf32.f32 "
        "{%0,%1,%2,%3}, {%4,%5,%6,%7}, {%8,%9}, {%0,%1,%2,%3};"
        : "+f"(d[0]), "+f"(d[1]), "+f"(d[2]), "+f"(d[3])
        : "r"(a[0]), "r"(a[1]), "r"(a[2]), "r"(a[3]), "r"(b[0]), "r"(b[1]));
}
__device__ __forceinline__ int swz(int g) { return g ^ (g >> 3); }

// ---------------- init: block 0 probes dtype, rest zero degree array --------
__global__ void k_init(const void* raw, int count, int nlimit, int* flag,
                       int* __restrict__ fill, int n) {
    if (blockIdx.x == 0) {
        __shared__ int ok;
        if (threadIdx.x == 0) ok = 1;
        __syncthreads();
        int m = count / 2 < 1024 ? count / 2 : 1024;
        const long long* p = (const long long*)raw;
        for (int i = threadIdx.x; i < m; i += blockDim.x) {
            long long v = p[i];
            if (v < 0 || v >= (long long)nlimit) ok = 0;
        }
        __syncthreads();
        if (threadIdx.x == 0) *flag = ok;
    } else {
        int i = (blockIdx.x - 1) * blockDim.x + threadIdx.x;
        if (i < n) fill[i] = 0;
    }
}

// ---------------- phase 2: edge convert+count | batch convert | preprocess --
__global__ void k_phase2(const void* eraw, int E, const int* flag,
                         int* __restrict__ src, int* __restrict__ dst,
                         int* __restrict__ deg,
                         const void* braw, int n, int* __restrict__ batch,
                         const float* __restrict__ x, float* __restrict__ xn,
                         int PB, int BB) {
    int b = blockIdx.x;
    if (b < PB) {
        int e0 = (b * blockDim.x + threadIdx.x) * 2;
        if (e0 >= E) return;
        int s0, d0, s1, d1;
        bool two = (e0 + 1 < E);
        if (*flag) {
            const long long* p = (const long long*)eraw;
            longlong2 sv = *(const longlong2*)(p + e0);
            longlong2 dv = *(const longlong2*)(p + E + e0);
            s0 = (int)sv.x; s1 = (int)sv.y;
            d0 = (int)dv.x; d1 = (int)dv.y;
        } else {
            const int* p = (const int*)eraw;
            s0 = p[e0]; d0 = p[E + e0];
            s1 = two ? p[e0 + 1] : 0;
            d1 = two ? p[E + e0 + 1] : 0;
        }
        src[e0] = s0; dst[e0] = d0;
        atomicAdd(&deg[d0], 1);
        if (two) {
            src[e0 + 1] = s1; dst[e0 + 1] = d1;
            atomicAdd(&deg[d1], 1);
        }
    } else if (b < PB + BB) {
        int i0 = ((b - PB) * blockDim.x + threadIdx.x) * 4;
        if (i0 >= n) return;
        if (*flag) {
            const long long* p = (const long long*)braw;
#pragma unroll
            for (int q = 0; q < 4; ++q)
                if (i0 + q < n) batch[i0 + q] = (int)p[i0 + q];
        } else {
            const int* p = (const int*)braw;
#pragma unroll
            for (int q = 0; q < 4; ++q)
                if (i0 + q < n) batch[i0 + q] = p[i0 + q];
        }
    } else {
        int w = (((b - PB - BB) * blockDim.x) + threadIdx.x) >> 5;
        if (w >= n) return;
        int lane = threadIdx.x & 31;
        float4 v = *(const float4*)(x + (size_t)w * 128 + lane * 4);
        float s = v.x + v.y + v.z + v.w;
#pragma unroll
        for (int o = 16; o > 0; o >>= 1) s += __shfl_xor_sync(0xffffffffu, s, o);
        float rinv = (s != 0.f) ? (1.f / s) : 0.f;
        *(float4*)(xn + (size_t)w * 128 + lane * 4) =
            make_float4(v.x * rinv, v.y * rinv, v.z * rinv, v.w * rinv);
    }
}

// ---------------- 2-phase scan ----------------
__global__ void k_scan_p1(const int* __restrict__ deg, int* __restrict__ rowptr,
                          int* __restrict__ fill, int* __restrict__ blksum, int n) {
    __shared__ int wsum[32];
    int t = threadIdx.x, lane = t & 31, wid = t >> 5;
    int i0 = blockIdx.x * SCAN_BLK + t * 4;
    int v[4];
    if (i0 + 3 < n) {
        int4 d = *(const int4*)(deg + i0);
        v[0] = d.x; v[1] = d.y; v[2] = d.z; v[3] = d.w;
    } else {
#pragma unroll
        for (int q = 0; q < 4; ++q) v[q] = (i0 + q < n) ? deg[i0 + q] : 0;
    }
    int s = v[0] + v[1] + v[2] + v[3];
    int xv = s;
#pragma unroll
    for (int o = 1; o < 32; o <<= 1) {
        int y = __shfl_up_sync(0xffffffffu, xv, o);
        if (lane >= o) xv += y;
    }
    if (lane == 31) wsum[wid] = xv;
    __syncthreads();
    if (wid == 0) {
        int wv = wsum[lane];
#pragma unroll
        for (int o = 1; o < 32; o <<= 1) {
            int y = __shfl_up_sync(0xffffffffu, wv, o);
            if (lane >= o) wv += y;
        }
        wsum[lane] = wv;
        if (lane == 31) blksum[blockIdx.x] = wv;
    }
    __syncthreads();
    int run = (xv - s) + (wid > 0 ? wsum[wid - 1] : 0);
    if (i0 + 3 < n) {
        int4 rp = make_int4(run, run + v[0], run + v[0] + v[1], run + v[0] + v[1] + v[2]);
        *(int4*)(rowptr + i0) = rp;
        *(int4*)(fill + i0) = rp;
    } else {
#pragma unroll
        for (int q = 0; q < 4; ++q)
            if (i0 + q < n) { rowptr[i0 + q] = run; fill[i0 + q] = run; run += v[q]; }
    }
}

__global__ void k_scan_p3(int* __restrict__ rowptr, int* __restrict__ fill,
                          const int* __restrict__ blksum, int n, int nb) {
    __shared__ int s_off, s_tot;
    if (threadIdx.x < 32) {
        int v = (threadIdx.x < nb) ? blksum[threadIdx.x] : 0;
        int xv = v;
#pragma unroll
        for (int o = 1; o < 32; o <<= 1) {
            int y = __shfl_up_sync(0xffffffffu, xv, o);
            if ((threadIdx.x & 31) >= o) xv += y;
        }
        if (threadIdx.x == 31) s_tot = xv;
        if (threadIdx.x == blockIdx.x) s_off = xv - v;
    }
    __syncthreads();
    int off = s_off;
    int i0 = blockIdx.x * SCAN_BLK + threadIdx.x * 4;
    if (blockIdx.x == 0) {
        if (threadIdx.x == 0) rowptr[n] = s_tot;
        return;
    }
    if (i0 + 3 < n) {
        int4 r = *(const int4*)(rowptr + i0);
        r.x += off; r.y += off; r.z += off; r.w += off;
        *(int4*)(rowptr + i0) = r;
        *(int4*)(fill + i0) = r;
    } else {
#pragma unroll
        for (int q = 0; q < 4; ++q)
            if (i0 + q < n) { int r = rowptr[i0 + q] + off; rowptr[i0 + q] = r; fill[i0 + q] = r; }
    }
}

__global__ void k_fill_edges(const int* __restrict__ src, const int* __restrict__ dst,
                             int* __restrict__ fillc, int* __restrict__ col, int E) {
    int e = blockIdx.x * blockDim.x + threadIdx.x;
    if (e < E) {
        int p = atomicAdd(&fillc[dst[e]], 1);
        col[p] = src[e];
    }
}

// ---------------- mean aggregation ----------------
__global__ void k_aggregate(const float* __restrict__ xin, const int* __restrict__ rowptr,
                            const int* __restrict__ col, float* __restrict__ outm, int n) {
    int w = (blockIdx.x * blockDim.x + threadIdx.x) >> 5;
    if (w >= n) return;
    int lane = threadIdx.x & 31;
    int s0 = rowptr[w], s1 = rowptr[w + 1];
    float ax = 0.f, ay = 0.f, az = 0.f, aw = 0.f;
    int j = s0;
    for (; j + 3 < s1; j += 4) {
        int i0 = __ldg(&col[j]);
        int i1 = __ldg(&col[j + 1]);
        int i2 = __ldg(&col[j + 2]);
        int i3 = __ldg(&col[j + 3]);
        float4 v0 = *(const float4*)(xin + (size_t)i0 * 128 + lane * 4);
        float4 v1 = *(const float4*)(xin + (size_t)i1 * 128 + lane * 4);
        float4 v2 = *(const float4*)(xin + (size_t)i2 * 128 + lane * 4);
        float4 v3 = *(const float4*)(xin + (size_t)i3 * 128 + lane * 4);
        ax += v0.x + v1.x + v2.x + v3.x;
        ay += v0.y + v1.y + v2.y + v3.y;
        az += v0.z + v1.z + v2.z + v3.z;
        aw += v0.w + v1.w + v2.w + v3.w;
    }
    for (; j < s1; ++j) {
        int s = __ldg(&col[j]);
        float4 v = *(const float4*)(xin + (size_t)s * 128 + lane * 4);
        ax += v.x; ay += v.y; az += v.z; aw += v.w;
    }
    float inv = 1.f / fmaxf((float)(s1 - s0), 1.f);
    *(float4*)(outm + (size_t)w * 128 + lane * 4) = make_float4(ax * inv, ay * inv, az * inv, aw * inv);
}

// ======= R11 GEMM (frozen best): 8x32-col chunks, inline staging =============
#define SM_WF     0
#define SM_AF0    32768
#define SM_AF1    (SM_AF0 + 4096)
#define SM_BS     (SM_AF1 + 4096)
#define SM_RSS    (SM_BS + 128)
#define SM_FLOATS (SM_RSS + 128)
#define FLAG_LEAKY 1
#define FLAG_NORM  2

__global__ void __launch_bounds__(256, 1)
k_gemm_mma(const float* __restrict__ A0, const float* __restrict__ A1,
           const float* __restrict__ Wa, const float* __restrict__ Wb, int ldw,
           const float* __restrict__ bias, float* __restrict__ out, int n, int flags) {
    extern __shared__ float sm[];
    float* Wf    = sm + SM_WF;
    float* bs    = sm + SM_BS;
    float* rowss = sm + SM_RSS;

    int tid = threadIdx.x, lane = tid & 31, wid = tid >> 5;
    int wm = wid >> 2, wn = wid & 3;

    if (tid < 128) bs[tid] = bias ? bias[tid] : 0.f;

    for (int it = 0; it < 32; ++it) {
        int idx4 = it * 256 + tid;
        int nn = idx4 >> 6;
        int k4 = (idx4 & 63) * 4;
        float4 v = (k4 < 128) ? *(const float4*)(Wa + (size_t)nn * ldw + k4)
                              : *(const float4*)(Wb + (size_t)nn * ldw + (k4 - 128));
        float vv[4] = {v.x, v.y, v.z, v.w};
#pragma unroll
        for (int q = 0; q < 4; ++q) {
            int k = k4 + q;
            int kb = k >> 3, kc = k & 7, nt = nn >> 3, nl = nn & 7;
            Wf[(kb * 16 + nt) * 64 + (nl * 4 + (kc & 3)) * 2 + (kc >> 2)] = __uint_as_float(f2tf32(vv[q]));
        }
    }
    __syncthreads();

    int numTiles = (n + 127) >> 7;
    int r = tid >> 1, ch = tid & 1;
    int mt_s = r >> 4, lrr = r & 7, rh = (r >> 3) & 1;

    for (int tile = blockIdx.x; tile < numTiles; tile += gridDim.x) {
        int row0 = tile << 7;
        float acc[4][4][4];
#pragma unroll
        for (int i = 0; i < 4; ++i)
#pragma unroll
            for (int j = 0; j < 4; ++j)
#pragma unroll
                for (int q = 0; q < 4; ++q) acc[i][j][q] = 0.f;

        {
            const float* rowp = A0 + (size_t)(row0 + r) * 128 + ch * 16;
            float* buf = sm + SM_AF0;
#pragma unroll
            for (int q = 0; q < 4; ++q) {
                float4 v = *(const float4*)(rowp + q * 4);
                float vv[4] = {v.x, v.y, v.z, v.w};
                int blk = (ch * 2 + (q >> 1)) * 8 + mt_s;
                int hh = q & 1;
#pragma unroll
                for (int j = 0; j < 4; ++j)
                    buf[blk * 128 + swz(lrr * 4 + j) * 4 + rh + 2 * hh] = __uint_as_float(f2tf32(vv[j]));
            }
        }
        __syncthreads();

        for (int c = 0; c < 8; ++c) {
            float pv[16];
            if (c < 7) {
                int cn = c + 1;
                const float* srcp = (cn < 4) ? A0 : A1;
                const float* rowp = srcp + (size_t)(row0 + r) * 128 + (cn & 3) * 32 + ch * 16;
#pragma unroll
                for (int q = 0; q < 4; ++q) {
                    float4 v = *(const float4*)(rowp + q * 4);
                    pv[q * 4 + 0] = v.x; pv[q * 4 + 1] = v.y; pv[q * 4 + 2] = v.z; pv[q * 4 + 3] = v.w;
                }
            }
            const float* Ab = sm + ((c & 1) ? SM_AF1 : SM_AF0);
#pragma unroll
            for (int h = 0; h < 4; ++h) {
                int kb = c * 4 + h;
                uint32_t a[4][4], b[4][2];
#pragma unroll
                for (int i = 0; i < 4; ++i) {
                    float4 af = *(const float4*)(Ab + (h * 8 + wm * 4 + i) * 128 + swz(lane) * 4);
                    a[i][0] = __float_as_uint(af.x);
                    a[i][1] = __float_as_uint(af.y);
                    a[i][2] = __float_as_uint(af.z);
                    a[i][3] = __float_as_uint(af.w);
                }
#pragma unroll
                for (int j = 0; j < 4; ++j) {
                    float2 bf = *(const float2*)(Wf + (kb * 16 + wn * 4 + j) * 64 + lane * 2);
                    b[j][0] = __float_as_uint(bf.x);
                    b[j][1] = __float_as_uint(bf.y);
                }
#pragma unroll
                for (int i = 0; i < 4; ++i)
#pragma unroll
                    for (int j = 0; j < 4; ++j)
                        mma_tf32_16n8k8(acc[i][j], a[i], b[j]);
            }
            if (c < 7) {
                float* buf = sm + (((c + 1) & 1) ? SM_AF1 : SM_AF0);
#pragma unroll
                for (int q = 0; q < 4; ++q) {
                    int blk = (ch * 2 + (q >> 1)) * 8 + mt_s;
                    int hh = q & 1;
#pragma unroll
                    for (int j = 0; j < 4; ++j)
                        buf[blk * 128 + swz(lrr * 4 + j) * 4 + rh + 2 * hh] = __uint_as_float(f2tf32(pv[q * 4 + j]));
                }
            }
            __syncthreads();
        }

        // ---------------- epilogue ----------------
        int lr = lane >> 2, lc = lane & 3;
        bool donorm = (flags & FLAG_NORM) != 0;
        if (donorm) {
            if (tid < 128) rowss[tid] = 0.f;
            __syncthreads();
#pragma unroll
            for (int i = 0; i < 4; ++i) {
#pragma unroll
                for (int rh2 = 0; rh2 < 2; ++rh2) {
                    float ss = 0.f;
#pragma unroll
                    for (int j = 0; j < 4; ++j) {
                        float d0 = acc[i][j][rh2 * 2], d1 = acc[i][j][rh2 * 2 + 1];
                        ss += d0 * d0 + d1 * d1;
                    }
                    ss += __shfl_xor_sync(0xffffffffu, ss, 1);
                    ss += __shfl_xor_sync(0xffffffffu, ss, 2);
                    if (lc == 0) atomicAdd(&rowss[wm * 64 + i * 16 + lr + rh2 * 8], ss);
                }
            }
            __syncthreads();
        }
#pragma unroll
        for (int i = 0; i < 4; ++i) {
#pragma unroll
            for (int rh2 = 0; rh2 < 2; ++rh2) {
                int rl = wm * 64 + i * 16 + lr + rh2 * 8;
                int row = row0 + rl;
                if (row >= n) continue;
                float inv = 1.f;
                if (donorm) inv = 1.f / fmaxf(sqrtf(rowss[rl]), 1e-12f);
#pragma unroll
                for (int j = 0; j < 4; ++j) {
                    int colp = wn * 32 + j * 8 + 2 * lc;
                    float v0 = acc[i][j][rh2 * 2] * inv + bs[colp];
                    float v1 = acc[i][j][rh2 * 2 + 1] * inv + bs[colp + 1];
                    v0 = (v0 >= 0.f) ? v0 : 0.01f * v0;
                    v1 = (v1 >= 0.f) ? v1 : 0.01f * v1;
                    *(float2*)(out + (size_t)row * 128 + colp) = make_float2(v0, v1);
                }
            }
        }
        __syncthreads();
    }
}

// ---------------- fused pool + final (128 blocks x 256 threads) -------------
__global__ void k_poolfinal(const float* __restrict__ hin, const int* __restrict__ batch,
                            const float* __restrict__ W, const float* __restrict__ b,
                            float* __restrict__ outp, int n) {
    __shared__ float pr2[256];
    __shared__ float pr[128];
    __shared__ float red[128];
    int g = blockIdx.x, tid = threadIdx.x;
    int f = tid & 127, half = tid >> 7;

    int lo = 0, hi = n;
    while (lo < hi) { int m = (lo + hi) >> 1; if (batch[m] < g) lo = m + 1; else hi = m; }
    int start = lo;
    hi = n;
    while (lo < hi) { int m = (lo + hi) >> 1; if (batch[m] < g + 1) lo = m + 1; else hi = m; }
    int end = lo;

    float acc = 0.f;
    for (int i = start + half; i < end; i += 2) acc += hin[(size_t)i * 128 + f];
    pr2[tid] = acc;
    __syncthreads();
    if (tid < 128) pr[tid] = pr2[tid] + pr2[tid + 128];
    __syncthreads();

    float a2 = 0.f;
    if (tid < 128) {
        a2 = b[tid];
#pragma unroll 8
        for (int k = 0; k < 128; ++k) a2 += pr[k] * __ldg(&W[tid * 128 + k]);
        a2 = (a2 >= 0.f) ? a2 : 0.01f * a2;
        red[tid] = a2 * a2;
    }
    __syncthreads();
    for (int s = 64; s > 0; s >>= 1) {
        if (tid < s) red[tid] += red[tid + s];
        __syncthreads();
    }
    if (tid < 128) {
        float inv = 1.f / fmaxf(sqrtf(red[0]), 1e-12f);
        outp[g * 128 + tid] = a2 * inv;
    }
}

// ---------------- launcher ----------------
extern "C" void kernel_launch(void* const* d_in, const int* in_sizes, int n_in,
                              void* d_out, int out_size) {
    const float* x         = (const float*)d_in[0];
    const void*  eidx_raw  = d_in[1];
    const void*  batch_raw = d_in[2];
    const float* W1l  = (const float*)d_in[3];
    const float* W1r  = (const float*)d_in[4];
    const float* W2l  = (const float*)d_in[5];
    const float* W2r  = (const float*)d_in[6];
    const float* fc1W = (const float*)d_in[7];
    const float* fc1b = (const float*)d_in[8];
    const float* fc2W = (const float*)d_in[9];
    const float* fc2b = (const float*)d_in[10];
    const float* fc3W = (const float*)d_in[11];
    const float* fc3b = (const float*)d_in[12];
    float* out = (float*)d_out;

    int n = in_sizes[0] / 128;
    int E = in_sizes[1] / 2;

    float *xn, *tb, *h1, *h, *mean;
    int *rowptr, *fill, *col, *srcA, *dstA, *batch32, *is64, *blksum;
    cudaGetSymbolAddress((void**)&xn,      g_xn);
    cudaGetSymbolAddress((void**)&tb,      g_t);
    cudaGetSymbolAddress((void**)&h1,      g_h1);
    cudaGetSymbolAddress((void**)&h,       g_h);
    cudaGetSymbolAddress((void**)&rowptr,  g_rowptr);
    cudaGetSymbolAddress((void**)&fill,    g_fill);
    cudaGetSymbolAddress((void**)&col,     g_col);
    cudaGetSymbolAddress((void**)&srcA,    g_src);
    cudaGetSymbolAddress((void**)&dstA,    g_dst);
    cudaGetSymbolAddress((void**)&batch32, g_batch);
    cudaGetSymbolAddress((void**)&is64,    g_is64);
    cudaGetSymbolAddress((void**)&blksum,  g_blksum);
    cudaGetSymbolAddress((void**)&mean,    g_mean);

    int smemFull = SM_FLOATS * (int)sizeof(float);
    cudaFuncSetAttribute(k_gemm_mma, cudaFuncAttributeMaxDynamicSharedMemorySize, smemFull);

    int warpBlocks = (n * 32 + 255) / 256;
    int intBlocks  = (n + 255) / 256;
    int edgeBlocks = (E + 255) / 256;
    int pairBlocks = (E / 2 + 255) / 256;
    int b4Blocks   = (n / 4 + 255) / 256 + 1;
    int scanBlocks = (n + SCAN_BLK - 1) / SCAN_BLK;

    k_init<<<intBlocks + 1, 256>>>(eidx_raw, 2 * E, n, is64, fill, n);
    k_phase2<<<pairBlocks + b4Blocks + warpBlocks, 256>>>(
        eidx_raw, E, is64, srcA, dstA, fill,
        batch_raw, n, batch32, x, xn, pairBlocks, b4Blocks);

    k_scan_p1<<<scanBlocks, 1024>>>(fill, rowptr, fill, blksum, n);
    k_scan_p3<<<scanBlocks, 1024>>>(rowptr, fill, blksum, n, scanBlocks);
    k_fill_edges<<<edgeBlocks, 256>>>(srcA, dstA, fill, col, E);

    // conv1
    k_aggregate<<<warpBlocks, 256>>>(xn, rowptr, col, mean, n);
    k_gemm_mma<<<148, 256, smemFull>>>(mean, xn, W1l, W1r, 128, nullptr, h1, n, FLAG_LEAKY | FLAG_NORM);

    // fc1
    k_gemm_mma<<<148, 256, smemFull>>>(h1, xn, fc1W, fc1W + 128, 256, fc1b, h, n, FLAG_LEAKY);

    // conv2
    k_aggregate<<<warpBlocks, 256>>>(h, rowptr, col, mean, n);
    k_gemm_mma<<<148, 256, smemFull>>>(mean, h, W2l, W2r, 128, nullptr, h1, n, FLAG_LEAKY | FLAG_NORM);

    // fc2
    k_gemm_mma<<<148, 256, smemFull>>>(h1, h, fc2W, fc2W + 128, 256, fc2b, tb, n, FLAG_LEAKY);

    // fused pool + final
    k_poolfinal<<<GMAX, 256>>>(tb, batch32, fc3W, fc3b, out, n);
}

// round 17
// speedup vs baseline: 1.1838x; 1.0050x over previous
#include <cuda_runtime.h>
#include <cuda_bf16.h>
#include <math.h>
#include <stdint.h>

#define NMAX 50000
#define NPAD 50176
#define EMAX 600000
#define GMAX 128
#define SCAN_BLK 4096

// ---------------- scratch ----------------
__device__ __align__(16) float g_xn[NPAD * 128];
__device__ __align__(16) float g_mean[NPAD * 128];
__device__ __align__(16) float g_t[NPAD * 128];
__device__ __align__(16) float g_h1[NPAD * 128];
__device__ __align__(16) float g_h[NPAD * 128];
__device__ __align__(16) int g_rowptr[NMAX + 8];
__device__ __align__(16) int g_fill[NMAX + 8];
__device__ int g_col[EMAX];
__device__ int g_src[EMAX];
__device__ int g_dst[EMAX];
__device__ int g_batch[NMAX + 8];
__device__ int g_blksum[64];
__device__ int g_is64;

// ---------------- tf32 helpers ----------------
__device__ __forceinline__ uint32_t f2tf32(float f) {
    uint32_t r;
    asm("cvt.rna.tf32.f32 %0, %1;" : "=r"(r) : "f"(f));
    return r;
}
__device__ __forceinline__ void mma_tf32_16n8k8(float* d, const uint32_t* a, const uint32_t* b) {
    asm volatile(
        "mma.sync.aligned.m16n8k8.row.col.f32.tf32.tf32.f32 "
        "{%0,%1,%2,%3}, {%4,%5,%6,%7}, {%8,%9}, {%0,%1,%2,%3};"
        : "+f"(d[0]), "+f"(d[1]), "+f"(d[2]), "+f"(d[3])
        : "r"(a[0]), "r"(a[1]), "r"(a[2]), "r"(a[3]), "r"(b[0]), "r"(b[1]));
}
__device__ __forceinline__ int swz(int g) { return g ^ (g >> 3); }

// ---------------- init: probe dtype, zero degree array, seed scan sentinels --
__global__ void k_init(const void* raw, int count, int nlimit, int* flag,
                       int* __restrict__ fill, int n, int* __restrict__ blksum) {
    if (blockIdx.x == 0) {
        __shared__ int ok;
        if (threadIdx.x == 0) ok = 1;
        __syncthreads();
        int m = count / 2 < 1024 ? count / 2 : 1024;
        const long long* p = (const long long*)raw;
        for (int i = threadIdx.x; i < m; i += blockDim.x) {
            long long v = p[i];
            if (v < 0 || v >= (long long)nlimit) ok = 0;
        }
        __syncthreads();
        if (threadIdx.x == 0) *flag = ok;
    } else {
        int i = (blockIdx.x - 1) * blockDim.x + threadIdx.x;
        if (i < n) fill[i] = 0;
        if (blockIdx.x == 1 && threadIdx.x < 64) blksum[threadIdx.x] = -1;  // sentinel
    }
}

// ---------------- phase 2: edge convert+count | batch convert | preprocess --
__global__ void k_phase2(const void* eraw, int E, const int* flag,
                         int* __restrict__ src, int* __restrict__ dst,
                         int* __restrict__ deg,
                         const void* braw, int n, int* __restrict__ batch,
                         const float* __restrict__ x, float* __restrict__ xn,
                         int PB, int BB) {
    int b = blockIdx.x;
    if (b < PB) {
        int e0 = (b * blockDim.x + threadIdx.x) * 2;
        if (e0 >= E) return;
        int s0, d0, s1, d1;
        bool two = (e0 + 1 < E);
        if (*flag) {
            const long long* p = (const long long*)eraw;
            longlong2 sv = *(const longlong2*)(p + e0);
            longlong2 dv = *(const longlong2*)(p + E + e0);
            s0 = (int)sv.x; s1 = (int)sv.y;
            d0 = (int)dv.x; d1 = (int)dv.y;
        } else {
            const int* p = (const int*)eraw;
            s0 = p[e0]; d0 = p[E + e0];
            s1 = two ? p[e0 + 1] : 0;
            d1 = two ? p[E + e0 + 1] : 0;
        }
        src[e0] = s0; dst[e0] = d0;
        atomicAdd(&deg[d0], 1);
        if (two) {
            src[e0 + 1] = s1; dst[e0 + 1] = d1;
            atomicAdd(&deg[d1], 1);
        }
    } else if (b < PB + BB) {
        int i0 = ((b - PB) * blockDim.x + threadIdx.x) * 4;
        if (i0 >= n) return;
        if (*flag) {
            const long long* p = (const long long*)braw;
#pragma unroll
            for (int q = 0; q < 4; ++q)
                if (i0 + q < n) batch[i0 + q] = (int)p[i0 + q];
        } else {
            const int* p = (const int*)braw;
#pragma unroll
            for (int q = 0; q < 4; ++q)
                if (i0 + q < n) batch[i0 + q] = p[i0 + q];
        }
    } else {
        int w = (((b - PB - BB) * blockDim.x) + threadIdx.x) >> 5;
        if (w >= n) return;
        int lane = threadIdx.x & 31;
        float4 v = *(const float4*)(x + (size_t)w * 128 + lane * 4);
        float s = v.x + v.y + v.z + v.w;
#pragma unroll
        for (int o = 16; o > 0; o >>= 1) s += __shfl_xor_sync(0xffffffffu, s, o);
        float rinv = (s != 0.f) ? (1.f / s) : 0.f;
        *(float4*)(xn + (size_t)w * 128 + lane * 4) =
            make_float4(v.x * rinv, v.y * rinv, v.z * rinv, v.w * rinv);
    }
}

// ---------------- single-kernel decoupled-lookback scan ----------------
// grid = nb (<=13) blocks, all co-resident -> spin-wait is safe.
__global__ void k_scan(int* __restrict__ deg_fill, int* __restrict__ rowptr,
                       int* blksum, int n) {
    __shared__ int wsum[32];
    __shared__ int s_off;
    int t = threadIdx.x, lane = t & 31, wid = t >> 5;
    int i0 = blockIdx.x * SCAN_BLK + t * 4;
    int v[4];
    if (i0 + 3 < n) {
        int4 d = *(const int4*)(deg_fill + i0);
        v[0] = d.x; v[1] = d.y; v[2] = d.z; v[3] = d.w;
    } else {
#pragma unroll
        for (int q = 0; q < 4; ++q) v[q] = (i0 + q < n) ? deg_fill[i0 + q] : 0;
    }
    int s = v[0] + v[1] + v[2] + v[3];
    int xv = s;
#pragma unroll
    for (int o = 1; o < 32; o <<= 1) {
        int y = __shfl_up_sync(0xffffffffu, xv, o);
        if (lane >= o) xv += y;
    }
    if (lane == 31) wsum[wid] = xv;
    __syncthreads();
    if (wid == 0) {
        int wv = wsum[lane];
#pragma unroll
        for (int o = 1; o < 32; o <<= 1) {
            int y = __shfl_up_sync(0xffffffffu, wv, o);
            if (lane >= o) wv += y;
        }
        wsum[lane] = wv;
        if (lane == 31) atomicExch(&blksum[blockIdx.x], wv);   // publish block total
        // lookback: sum totals of lower-indexed blocks
        int val = 0;
        if (lane < blockIdx.x) {
            int tv;
            do { tv = atomicAdd(&blksum[lane], 0); } while (tv < 0);
            val = tv;
        }
#pragma unroll
        for (int o = 16; o > 0; o >>= 1) val += __shfl_xor_sync(0xffffffffu, val, o);
        if (lane == 0) s_off = val;
    }
    __syncthreads();
    int off = s_off;
    int run = off + (xv - s) + (wid > 0 ? wsum[wid - 1] : 0);
    if (i0 + 3 < n) {
        int4 rp = make_int4(run, run + v[0], run + v[0] + v[1], run + v[0] + v[1] + v[2]);
        *(int4*)(rowptr + i0) = rp;
        *(int4*)(deg_fill + i0) = rp;
    } else {
#pragma unroll
        for (int q = 0; q < 4; ++q)
            if (i0 + q < n) { rowptr[i0 + q] = run; deg_fill[i0 + q] = run; run += v[q]; }
    }
    if (blockIdx.x == gridDim.x - 1 && t == 0) rowptr[n] = off + wsum[31];
}

__global__ void k_fill_edges(const int* __restrict__ src, const int* __restrict__ dst,
                             int* __restrict__ fillc, int* __restrict__ col, int E) {
    int e = blockIdx.x * blockDim.x + threadIdx.x;
    if (e < E) {
        int p = atomicAdd(&fillc[dst[e]], 1);
        col[p] = src[e];
    }
}

// ---------------- mean aggregation ----------------
__global__ void k_aggregate(const float* __restrict__ xin, const int* __restrict__ rowptr,
                            const int* __restrict__ col, float* __restrict__ outm, int n) {
    int w = (blockIdx.x * blockDim.x + threadIdx.x) >> 5;
    if (w >= n) return;
    int lane = threadIdx.x & 31;
    int s0 = rowptr[w], s1 = rowptr[w + 1];
    float ax = 0.f, ay = 0.f, az = 0.f, aw = 0.f;
    int j = s0;
    for (; j + 3 < s1; j += 4) {
        int i0 = __ldg(&col[j]);
        int i1 = __ldg(&col[j + 1]);
        int i2 = __ldg(&col[j + 2]);
        int i3 = __ldg(&col[j + 3]);
        float4 v0 = *(const float4*)(xin + (size_t)i0 * 128 + lane * 4);
        float4 v1 = *(const float4*)(xin + (size_t)i1 * 128 + lane * 4);
        float4 v2 = *(const float4*)(xin + (size_t)i2 * 128 + lane * 4);
        float4 v3 = *(const float4*)(xin + (size_t)i3 * 128 + lane * 4);
        ax += v0.x + v1.x + v2.x + v3.x;
        ay += v0.y + v1.y + v2.y + v3.y;
        az += v0.z + v1.z + v2.z + v3.z;
        aw += v0.w + v1.w + v2.w + v3.w;
    }
    for (; j < s1; ++j) {
        int s = __ldg(&col[j]);
        float4 v = *(const float4*)(xin + (size_t)s * 128 + lane * 4);
        ax += v.x; ay += v.y; az += v.z; aw += v.w;
    }
    float inv = 1.f / fmaxf((float)(s1 - s0), 1.f);
    *(float4*)(outm + (size_t)w * 128 + lane * 4) = make_float4(ax * inv, ay * inv, az * inv, aw * inv);
}

// ======= R11 GEMM (frozen best): 8x32-col chunks, inline staging =============
#define SM_WF     0
#define SM_AF0    32768
#define SM_AF1    (SM_AF0 + 4096)
#define SM_BS     (SM_AF1 + 4096)
#define SM_RSS    (SM_BS + 128)
#define SM_FLOATS (SM_RSS + 128)
#define FLAG_LEAKY 1
#define FLAG_NORM  2

__global__ void __launch_bounds__(256, 1)
k_gemm_mma(const float* __restrict__ A0, const float* __restrict__ A1,
           const float* __restrict__ Wa, const float* __restrict__ Wb, int ldw,
           const float* __restrict__ bias, float* __restrict__ out, int n, int flags) {
    extern __shared__ float sm[];
    float* Wf    = sm + SM_WF;
    float* bs    = sm + SM_BS;
    float* rowss = sm + SM_RSS;

    int tid = threadIdx.x, lane = tid & 31, wid = tid >> 5;
    int wm = wid >> 2, wn = wid & 3;

    if (tid < 128) bs[tid] = bias ? bias[tid] : 0.f;

    for (int it = 0; it < 32; ++it) {
        int idx4 = it * 256 + tid;
        int nn = idx4 >> 6;
        int k4 = (idx4 & 63) * 4;
        float4 v = (k4 < 128) ? *(const float4*)(Wa + (size_t)nn * ldw + k4)
                              : *(const float4*)(Wb + (size_t)nn * ldw + (k4 - 128));
        float vv[4] = {v.x, v.y, v.z, v.w};
#pragma unroll
        for (int q = 0; q < 4; ++q) {
            int k = k4 + q;
            int kb = k >> 3, kc = k & 7, nt = nn >> 3, nl = nn & 7;
            Wf[(kb * 16 + nt) * 64 + (nl * 4 + (kc & 3)) * 2 + (kc >> 2)] = __uint_as_float(f2tf32(vv[q]));
        }
    }
    __syncthreads();

    int numTiles = (n + 127) >> 7;
    int r = tid >> 1, ch = tid & 1;
    int mt_s = r >> 4, lrr = r & 7, rh = (r >> 3) & 1;

    for (int tile = blockIdx.x; tile < numTiles; tile += gridDim.x) {
        int row0 = tile << 7;
        float acc[4][4][4];
#pragma unroll
        for (int i = 0; i < 4; ++i)
#pragma unroll
            for (int j = 0; j < 4; ++j)
#pragma unroll
                for (int q = 0; q < 4; ++q) acc[i][j][q] = 0.f;

        {
            const float* rowp = A0 + (size_t)(row0 + r) * 128 + ch * 16;
            float* buf = sm + SM_AF0;
#pragma unroll
            for (int q = 0; q < 4; ++q) {
                float4 v = *(const float4*)(rowp + q * 4);
                float vv[4] = {v.x, v.y, v.z, v.w};
                int blk = (ch * 2 + (q >> 1)) * 8 + mt_s;
                int hh = q & 1;
#pragma unroll
                for (int j = 0; j < 4; ++j)
                    buf[blk * 128 + swz(lrr * 4 + j) * 4 + rh + 2 * hh] = __uint_as_float(f2tf32(vv[j]));
            }
        }
        __syncthreads();

        for (int c = 0; c < 8; ++c) {
            float pv[16];
            if (c < 7) {
                int cn = c + 1;
                const float* srcp = (cn < 4) ? A0 : A1;
                const float* rowp = srcp + (size_t)(row0 + r) * 128 + (cn & 3) * 32 + ch * 16;
#pragma unroll
                for (int q = 0; q < 4; ++q) {
                    float4 v = *(const float4*)(rowp + q * 4);
                    pv[q * 4 + 0] = v.x; pv[q * 4 + 1] = v.y; pv[q * 4 + 2] = v.z; pv[q * 4 + 3] = v.w;
                }
            }
            const float* Ab = sm + ((c & 1) ? SM_AF1 : SM_AF0);
#pragma unroll
            for (int h = 0; h < 4; ++h) {
                int kb = c * 4 + h;
                uint32_t a[4][4], b[4][2];
#pragma unroll
                for (int i = 0; i < 4; ++i) {
                    float4 af = *(const float4*)(Ab + (h * 8 + wm * 4 + i) * 128 + swz(lane) * 4);
                    a[i][0] = __float_as_uint(af.x);
                    a[i][1] = __float_as_uint(af.y);
                    a[i][2] = __float_as_uint(af.z);
                    a[i][3] = __float_as_uint(af.w);
                }
#pragma unroll
                for (int j = 0; j < 4; ++j) {
                    float2 bf = *(const float2*)(Wf + (kb * 16 + wn * 4 + j) * 64 + lane * 2);
                    b[j][0] = __float_as_uint(bf.x);
                    b[j][1] = __float_as_uint(bf.y);
                }
#pragma unroll
                for (int i = 0; i < 4; ++i)
#pragma unroll
                    for (int j = 0; j < 4; ++j)
                        mma_tf32_16n8k8(acc[i][j], a[i], b[j]);
            }
            if (c < 7) {
                float* buf = sm + (((c + 1) & 1) ? SM_AF1 : SM_AF0);
#pragma unroll
                for (int q = 0; q < 4; ++q) {
                    int blk = (ch * 2 + (q >> 1)) * 8 + mt_s;
                    int hh = q & 1;
#pragma unroll
                    for (int j = 0; j < 4; ++j)
                        buf[blk * 128 + swz(lrr * 4 + j) * 4 + rh + 2 * hh] = __uint_as_float(f2tf32(pv[q * 4 + j]));
                }
            }
            __syncthreads();
        }

        // ---------------- epilogue ----------------
        int lr = lane >> 2, lc = lane & 3;
        bool donorm = (flags & FLAG_NORM) != 0;
        if (donorm) {
            if (tid < 128) rowss[tid] = 0.f;
            __syncthreads();
#pragma unroll
            for (int i = 0; i < 4; ++i) {
#pragma unroll
                for (int rh2 = 0; rh2 < 2; ++rh2) {
                    float ss = 0.f;
#pragma unroll
                    for (int j = 0; j < 4; ++j) {
                        float d0 = acc[i][j][rh2 * 2], d1 = acc[i][j][rh2 * 2 + 1];
                        ss += d0 * d0 + d1 * d1;
                    }
                    ss += __shfl_xor_sync(0xffffffffu, ss, 1);
                    ss += __shfl_xor_sync(0xffffffffu, ss, 2);
                    if (lc == 0) atomicAdd(&rowss[wm * 64 + i * 16 + lr + rh2 * 8], ss);
                }
            }
            __syncthreads();
        }
#pragma unroll
        for (int i = 0; i < 4; ++i) {
#pragma unroll
            for (int rh2 = 0; rh2 < 2; ++rh2) {
                int rl = wm * 64 + i * 16 + lr + rh2 * 8;
                int row = row0 + rl;
                if (row >= n) continue;
                float inv = 1.f;
                if (donorm) inv = 1.f / fmaxf(sqrtf(rowss[rl]), 1e-12f);
#pragma unroll
                for (int j = 0; j < 4; ++j) {
                    int colp = wn * 32 + j * 8 + 2 * lc;
                    float v0 = acc[i][j][rh2 * 2] * inv + bs[colp];
                    float v1 = acc[i][j][rh2 * 2 + 1] * inv + bs[colp + 1];
                    v0 = (v0 >= 0.f) ? v0 : 0.01f * v0;
                    v1 = (v1 >= 0.f) ? v1 : 0.01f * v1;
                    *(float2*)(out + (size_t)row * 128 + colp) = make_float2(v0, v1);
                }
            }
        }
        __syncthreads();
    }
}

// ---------------- fused pool + final (128 blocks x 256 threads) -------------
__global__ void k_poolfinal(const float* __restrict__ hin, const int* __restrict__ batch,
                            const float* __restrict__ W, const float* __restrict__ b,
                            float* __restrict__ outp, int n) {
    __shared__ float pr2[256];
    __shared__ float pr[128];
    __shared__ float red[128];
    int g = blockIdx.x, tid = threadIdx.x;
    int f = tid & 127, half = tid >> 7;

    int lo = 0, hi = n;
    while (lo < hi) { int m = (lo + hi) >> 1; if (batch[m] < g) lo = m + 1; else hi = m; }
    int start = lo;
    hi = n;
    while (lo < hi) { int m = (lo + hi) >> 1; if (batch[m] < g + 1) lo = m + 1; else hi = m; }
    int end = lo;

    float acc = 0.f;
    for (int i = start + half; i < end; i += 2) acc += hin[(size_t)i * 128 + f];
    pr2[tid] = acc;
    __syncthreads();
    if (tid < 128) pr[tid] = pr2[tid] + pr2[tid + 128];
    __syncthreads();

    float a2 = 0.f;
    if (tid < 128) {
        a2 = b[tid];
#pragma unroll 8
        for (int k = 0; k < 128; ++k) a2 += pr[k] * __ldg(&W[tid * 128 + k]);
        a2 = (a2 >= 0.f) ? a2 : 0.01f * a2;
        red[tid] = a2 * a2;
    }
    __syncthreads();
    for (int s = 64; s > 0; s >>= 1) {
        if (tid < s) red[tid] += red[tid + s];
        __syncthreads();
    }
    if (tid < 128) {
        float inv = 1.f / fmaxf(sqrtf(red[0]), 1e-12f);
        outp[g * 128 + tid] = a2 * inv;
    }
}

// ---------------- launcher ----------------
extern "C" void kernel_launch(void* const* d_in, const int* in_sizes, int n_in,
                              void* d_out, int out_size) {
    const float* x         = (const float*)d_in[0];
    const void*  eidx_raw  = d_in[1];
    const void*  batch_raw = d_in[2];
    const float* W1l  = (const float*)d_in[3];
    const float* W1r  = (const float*)d_in[4];
    const float* W2l  = (const float*)d_in[5];
    const float* W2r  = (const float*)d_in[6];
    const float* fc1W = (const float*)d_in[7];
    const float* fc1b = (const float*)d_in[8];
    const float* fc2W = (const float*)d_in[9];
    const float* fc2b = (const float*)d_in[10];
    const float* fc3W = (const float*)d_in[11];
    const float* fc3b = (const float*)d_in[12];
    float* out = (float*)d_out;

    int n = in_sizes[0] / 128;
    int E = in_sizes[1] / 2;

    float *xn, *tb, *h1, *h, *mean;
    int *rowptr, *fill, *col, *srcA, *dstA, *batch32, *is64, *blksum;
    cudaGetSymbolAddress((void**)&xn,      g_xn);
    cudaGetSymbolAddress((void**)&tb,      g_t);
    cudaGetSymbolAddress((void**)&h1,      g_h1);
    cudaGetSymbolAddress((void**)&h,       g_h);
    cudaGetSymbolAddress((void**)&rowptr,  g_rowptr);
    cudaGetSymbolAddress((void**)&fill,    g_fill);
    cudaGetSymbolAddress((void**)&col,     g_col);
    cudaGetSymbolAddress((void**)&srcA,    g_src);
    cudaGetSymbolAddress((void**)&dstA,    g_dst);
    cudaGetSymbolAddress((void**)&batch32, g_batch);
    cudaGetSymbolAddress((void**)&is64,    g_is64);
    cudaGetSymbolAddress((void**)&blksum,  g_blksum);
    cudaGetSymbolAddress((void**)&mean,    g_mean);

    int smemFull = SM_FLOATS * (int)sizeof(float);
    cudaFuncSetAttribute(k_gemm_mma, cudaFuncAttributeMaxDynamicSharedMemorySize, smemFull);

    int warpBlocks = (n * 32 + 255) / 256;
    int intBlocks  = (n + 255) / 256;
    int edgeBlocks = (E + 255) / 256;
    int pairBlocks = (E / 2 + 255) / 256;
    int b4Blocks   = (n / 4 + 255) / 256 + 1;
    int scanBlocks = (n + SCAN_BLK - 1) / SCAN_BLK;

    k_init<<<intBlocks + 1, 256>>>(eidx_raw, 2 * E, n, is64, fill, n, blksum);
    k_phase2<<<pairBlocks + b4Blocks + warpBlocks, 256>>>(
        eidx_raw, E, is64, srcA, dstA, fill,
        batch_raw, n, batch32, x, xn, pairBlocks, b4Blocks);

    k_scan<<<scanBlocks, 1024>>>(fill, rowptr, blksum, n);
    k_fill_edges<<<edgeBlocks, 256>>>(srcA, dstA, fill, col, E);

    // conv1
    k_aggregate<<<warpBlocks, 256>>>(xn, rowptr, col, mean, n);
    k_gemm_mma<<<148, 256, smemFull>>>(mean, xn, W1l, W1r, 128, nullptr, h1, n, FLAG_LEAKY | FLAG_NORM);

    // fc1
    k_gemm_mma<<<148, 256, smemFull>>>(h1, xn, fc1W, fc1W + 128, 256, fc1b, h, n, FLAG_LEAKY);

    // conv2
    k_aggregate<<<warpBlocks, 256>>>(h, rowptr, col, mean, n);
    k_gemm_mma<<<148, 256, smemFull>>>(mean, h, W2l, W2r, 128, nullptr, h1, n, FLAG_LEAKY | FLAG_NORM);

    // fc2
    k_gemm_mma<<<148, 256, smemFull>>>(h1, h, fc2W, fc2W + 128, 256, fc2b, tb, n, FLAG_LEAKY);

    // fused pool + final
    k_poolfinal<<<GMAX, 256>>>(tb, batch32, fc3W, fc3b, out, n);
}